// round 16
// baseline (speedup 1.0000x reference)
#include <cuda_runtime.h>
#include <cstdint>

// Two-stream chunked pipeline (4 chunks x 16 batches), pure event DAG:
//   stream0: conv(c) -> select(c) -> record ev[c]         (c = 0..3)
//   streamB: wait ev[c] -> mul(c)
//   stream0 waits final event from streamB.
// conv(c+1) overlaps mul(c): the conv read stream and mul read/write stream
// share the DRAM bus instead of serializing (490MB compulsory ~ 78us floor).
__device__ float    d_gate[64 * 16384];
__device__ unsigned d_thr[64];

__device__ __forceinline__ unsigned f2key(float f) {
    unsigned u = __float_as_uint(f);
    return (u & 0x80000000u) ? ~u : (u | 0x80000000u);  // monotone float->uint
}

// ---------------------------------------------------------------------------
// conv chunk: 16 batches, 1024 blocks x 256. One thread per gate pixel,
// 12 coalesced float4 loads (measured at the 6.3TB/s read ceiling).
// ---------------------------------------------------------------------------
__global__ void gate_conv_kernel(const float4* __restrict__ in,
                                 const float* __restrict__ wk, int batch0) {
    __shared__ float4 w[12];
    int t = threadIdx.x;
    if (t < 12) w[t] = reinterpret_cast<const float4*>(wk)[t];
    __syncthreads();

    int idx = blockIdx.x * blockDim.x + t;      // [0, 16*16384)
    int x = idx & 127;
    int y = (idx >> 7) & 127;
    int b = batch0 + (idx >> 14);

    const float4* base = in + (size_t)b * 196608 + x;
    float sum = 0.0f;
#pragma unroll
    for (int c = 0; c < 3; c++) {
#pragma unroll
        for (int i = 0; i < 4; i++) {
            float4 v = base[c * 65536 + (4 * y + i) * 128];
            float4 ww = w[c * 4 + i];
            sum += v.x * ww.x + v.y * ww.y + v.z * ww.z + v.w * ww.w;
        }
    }
    d_gate[b * 16384 + (idx & 16383)] = sum;
}

// ---------------------------------------------------------------------------
// select chunk: 16 blocks x 1024 threads, one block per batch.
// MSB-first radix select, 16 register keys/thread, warp-private histograms
// (match_any leader updates), single-warp shfl suffix scan.
// ---------------------------------------------------------------------------
__global__ void __launch_bounds__(1024) gate_select_kernel(int batch0) {
    __shared__ unsigned hist[32][256];
    __shared__ int cnt[256];
    __shared__ unsigned s_prefix;
    __shared__ int s_k;

    const int row = batch0 + blockIdx.x;
    const int t = threadIdx.x;          // blockDim = 1024
    const int warp = t >> 5;
    const int lane = t & 31;

    unsigned key[16];
    const float4* g4 = reinterpret_cast<const float4*>(d_gate + row * 16384);
#pragma unroll
    for (int i = 0; i < 4; i++) {
        float4 v = g4[t + i * 1024];
        key[4 * i + 0] = f2key(v.x);
        key[4 * i + 1] = f2key(v.y);
        key[4 * i + 2] = f2key(v.z);
        key[4 * i + 3] = f2key(v.w);
    }

    if (t == 0) { s_prefix = 0u; s_k = 4096; }

#pragma unroll
    for (int pass = 0; pass < 4; pass++) {
        const int shift = 24 - 8 * pass;
#pragma unroll
        for (int i = t; i < 32 * 256; i += 1024)
            (&hist[0][0])[i] = 0u;
        __syncthreads();

        const unsigned pmask = pass ? (0xFFFFFFFFu << (32 - 8 * pass)) : 0u;
        const unsigned prefix = s_prefix;
        const int kcur = s_k;

#pragma unroll
        for (int i = 0; i < 16; i++) {
            unsigned u = key[i];
            unsigned bn = ((u & pmask) == prefix) ? ((u >> shift) & 0xFFu)
                                                  : 0xFFFFFFFFu;
            unsigned same = __match_any_sync(0xFFFFFFFFu, bn);
            if (bn != 0xFFFFFFFFu && lane == (__ffs(same) - 1))
                hist[warp][bn] += __popc(same);      // warp-private
        }
        __syncthreads();

        if (t < 256) {
            int c = 0;
#pragma unroll
            for (int wg = 0; wg < 32; wg++) c += hist[wg][t];
            cnt[t] = c;
        }
        __syncthreads();

        if (warp == 0) {
            int v[8], s[8];
#pragma unroll
            for (int j = 0; j < 8; j++) v[j] = cnt[lane * 8 + j];
            s[7] = v[7];
#pragma unroll
            for (int j = 6; j >= 0; j--) s[j] = s[j + 1] + v[j];
            int suf = s[0];
#pragma unroll
            for (int off = 1; off < 32; off <<= 1) {
                int o = __shfl_down_sync(0xFFFFFFFFu, suf, off);
                if (lane + off < 32) suf += o;
            }
            int above = suf - s[0];
#pragma unroll
            for (int j = 0; j < 8; j++) {
                int Sj = s[j] + above;
                int Sn = (j < 7 ? s[j + 1] : 0) + above;
                if (Sj >= kcur && Sn < kcur) {
                    s_prefix = prefix | ((unsigned)(lane * 8 + j) << shift);
                    s_k = kcur - Sn;
                }
            }
        }
        __syncthreads();
    }

    if (t == 0) d_thr[row] = s_prefix;   // exact key of K-th largest
}

// ---------------------------------------------------------------------------
// mul chunk: grid (64, 3, 16). One thread = one gate cell x 4 image rows:
// MLP=4 predicated loads (sector-exact skip), coalesced 512B/instruction.
// ---------------------------------------------------------------------------
__global__ void gate_mul_kernel(const float4* __restrict__ in,
                                float4* __restrict__ out, int batch0) {
    int i  = blockIdx.x * blockDim.x + threadIdx.x;  // [0, 128*128)
    int x4 = i & 127;              // float4 col == gate col
    int gy = i >> 7;               // gate row
    int c  = blockIdx.y;           // channel
    int b  = batch0 + blockIdx.z;  // batch

    unsigned thr = __ldg(&d_thr[b]);
    float gv = d_gate[b * 16384 + gy * 128 + x4];
    bool alive = f2key(gv) >= thr;

    size_t base = (size_t)(b * 3 + c) * 65536 + (size_t)(4 * gy) * 128 + x4;

    float4 z = make_float4(0.f, 0.f, 0.f, 0.f);
    float4 v0 = z, v1 = z, v2 = z, v3 = z;
    if (alive) {
        float4 t0 = in[base];
        float4 t1 = in[base + 128];
        float4 t2 = in[base + 256];
        float4 t3 = in[base + 384];
        v0.x = t0.x * gv; v0.y = t0.y * gv; v0.z = t0.z * gv; v0.w = t0.w * gv;
        v1.x = t1.x * gv; v1.y = t1.y * gv; v1.z = t1.z * gv; v1.w = t1.w * gv;
        v2.x = t2.x * gv; v2.y = t2.y * gv; v2.z = t2.z * gv; v2.w = t2.w * gv;
        v3.x = t3.x * gv; v3.y = t3.y * gv; v3.z = t3.z * gv; v3.w = t3.w * gv;
    }
    __stcs(&out[base],       v0);
    __stcs(&out[base + 128], v1);
    __stcs(&out[base + 256], v2);
    __stcs(&out[base + 384], v3);
}

// ---------------------------------------------------------------------------
extern "C" void kernel_launch(void* const* d_in, const int* in_sizes, int n_in,
                              void* d_out, int out_size) {
    const float* inp = (const float*)d_in[0];
    const float* wk  = (const float*)d_in[1];
    if (n_in >= 2 && in_sizes[0] == 48) {  // defensive: swap if order flipped
        inp = (const float*)d_in[1];
        wk  = (const float*)d_in[0];
    }

    // Second stream + events for the fork/join DAG. Created per call and
    // intentionally not destroyed (destroying a stream/event participating
    // in an active capture invalidates it; kernel_launch is invoked only a
    // handful of times, graph replays don't re-enter).
    cudaStream_t sB = 0;
    bool multi = (cudaStreamCreateWithFlags(&sB, cudaStreamNonBlocking)
                  == cudaSuccess);
    cudaEvent_t ev[4], evFin;
    if (multi) {
        for (int c = 0; c < 4 && multi; c++)
            multi = (cudaEventCreateWithFlags(&ev[c], cudaEventDisableTiming)
                     == cudaSuccess);
        if (multi)
            multi = (cudaEventCreateWithFlags(&evFin, cudaEventDisableTiming)
                     == cudaSuccess);
    }

    if (multi) {
        for (int c = 0; c < 4; c++) {
            const int batch0 = c * 16;
            gate_conv_kernel<<<1024, 256>>>((const float4*)inp, wk, batch0);
            gate_select_kernel<<<16, 1024>>>(batch0);
            cudaEventRecord(ev[c], 0);
            cudaStreamWaitEvent(sB, ev[c], 0);
            dim3 mgrid(64, 3, 16);
            gate_mul_kernel<<<mgrid, 256, 0, sB>>>((const float4*)inp,
                                                   (float4*)d_out, batch0);
        }
        cudaEventRecord(evFin, sB);
        cudaStreamWaitEvent(0, evFin, 0);      // join back to origin stream
    } else {
        // sequential fallback (R14-class)
        for (int c = 0; c < 4; c++) {
            const int batch0 = c * 16;
            gate_conv_kernel<<<1024, 256>>>((const float4*)inp, wk, batch0);
            gate_select_kernel<<<16, 1024>>>(batch0);
            dim3 mgrid(64, 3, 16);
            gate_mul_kernel<<<mgrid, 256>>>((const float4*)inp,
                                            (float4*)d_out, batch0);
        }
    }
}

// round 17
// speedup vs baseline: 1.3196x; 1.3196x over previous
#include <cuda_runtime.h>
#include <cstdint>

// Gate pipeline, 3 kernels chained with Programmatic Dependent Launch.
// FINAL CONFIGURATION (= R14, session best 109.3us):
//   K1 conv:   4x4/s4 [64,3,512,512] -> gate[64,128,128]  (~34us, at the
//              measured 6.3TB/s chip read ceiling)
//   K2 select: per-batch exact K-th-largest key, 64x1024, register keys,
//              warp-private match_any histograms, shfl suffix scan (~4us)
//   K3 mul:    out = in * (gate >= thr ? gate : 0), 1 gate cell x 4 rows
//              per thread (MLP=4), predicated sector-exact read skip (~56us,
//              mixed-stream floor)
// PDL: consumers launch during producer drain; cudaGridDependencySynchronize
// guarantees producer-grid completion (and store visibility) before use.
__device__ float    d_gate[64 * 16384];
__device__ unsigned d_thr[64];

__device__ __forceinline__ unsigned f2key(float f) {
    unsigned u = __float_as_uint(f);
    return (u & 0x80000000u) ? ~u : (u | 0x80000000u);  // monotone float->uint
}

// ---------------------------------------------------------------------------
// K1: conv. One thread per gate pixel, 12 coalesced float4 loads.
// ---------------------------------------------------------------------------
__global__ void gate_conv_kernel(const float4* __restrict__ in,
                                 const float* __restrict__ wk) {
    __shared__ float4 w[12];
    int t = threadIdx.x;
    if (t < 12) w[t] = reinterpret_cast<const float4*>(wk)[t];
    __syncthreads();

    int idx = blockIdx.x * blockDim.x + t;      // [0, 64*16384)
    int x = idx & 127;
    int y = (idx >> 7) & 127;
    int b = idx >> 14;

    const float4* base = in + (size_t)b * 196608 + x;
    float sum = 0.0f;
#pragma unroll
    for (int c = 0; c < 3; c++) {
#pragma unroll
        for (int i = 0; i < 4; i++) {
            float4 v = base[c * 65536 + (4 * y + i) * 128];
            float4 ww = w[c * 4 + i];
            sum += v.x * ww.x + v.y * ww.y + v.z * ww.z + v.w * ww.w;
        }
    }
    d_gate[idx] = sum;

#if __CUDA_ARCH__ >= 900
    cudaTriggerProgrammaticLaunchCompletion();   // let K2 start filling SMs
#endif
}

// ---------------------------------------------------------------------------
// K2: per-batch K-th-largest key, MSB-first radix select, 4x8-bit.
// 64 blocks x 1024 threads: 16 register keys/thread. Warp-private histograms
// (no atomics), single-warp shfl suffix scan (4 barriers/pass).
// ---------------------------------------------------------------------------
__global__ void __launch_bounds__(1024) gate_select_kernel() {
    __shared__ unsigned hist[32][256];   // per-warp private, 32KB
    __shared__ int cnt[256];
    __shared__ unsigned s_prefix;
    __shared__ int s_k;

    const int row = blockIdx.x;
    const int t = threadIdx.x;          // blockDim = 1024
    const int warp = t >> 5;
    const int lane = t & 31;

#if __CUDA_ARCH__ >= 900
    cudaGridDependencySynchronize();     // wait for conv grid completion
#endif

    // one-shot vectorized key load: 4 float4 = 16 keys per thread
    unsigned key[16];
    const float4* g4 = reinterpret_cast<const float4*>(d_gate + row * 16384);
#pragma unroll
    for (int i = 0; i < 4; i++) {
        float4 v = g4[t + i * 1024];
        key[4 * i + 0] = f2key(v.x);
        key[4 * i + 1] = f2key(v.y);
        key[4 * i + 2] = f2key(v.z);
        key[4 * i + 3] = f2key(v.w);
    }

    if (t == 0) { s_prefix = 0u; s_k = 4096; }

#pragma unroll
    for (int pass = 0; pass < 4; pass++) {
        const int shift = 24 - 8 * pass;
#pragma unroll
        for (int i = t; i < 32 * 256; i += 1024)
            (&hist[0][0])[i] = 0u;
        __syncthreads();

        const unsigned pmask = pass ? (0xFFFFFFFFu << (32 - 8 * pass)) : 0u;
        const unsigned prefix = s_prefix;
        const int kcur = s_k;

#pragma unroll
        for (int i = 0; i < 16; i++) {
            unsigned u = key[i];
            unsigned bn = ((u & pmask) == prefix) ? ((u >> shift) & 0xFFu)
                                                  : 0xFFFFFFFFu;
            unsigned same = __match_any_sync(0xFFFFFFFFu, bn);
            if (bn != 0xFFFFFFFFu && lane == (__ffs(same) - 1))
                hist[warp][bn] += __popc(same);      // warp-private
        }
        __syncthreads();

        if (t < 256) {
            int c = 0;
#pragma unroll
            for (int wg = 0; wg < 32; wg++) c += hist[wg][t];
            cnt[t] = c;
        }
        __syncthreads();

        // warp 0: suffix scan over 256 bins (8 bins/lane) + pick bin
        if (warp == 0) {
            int v[8], s[8];
#pragma unroll
            for (int j = 0; j < 8; j++) v[j] = cnt[lane * 8 + j];
            s[7] = v[7];
#pragma unroll
            for (int j = 6; j >= 0; j--) s[j] = s[j + 1] + v[j];
            int suf = s[0];
#pragma unroll
            for (int off = 1; off < 32; off <<= 1) {
                int o = __shfl_down_sync(0xFFFFFFFFu, suf, off);
                if (lane + off < 32) suf += o;
            }
            int above = suf - s[0];
#pragma unroll
            for (int j = 0; j < 8; j++) {
                int Sj = s[j] + above;
                int Sn = (j < 7 ? s[j + 1] : 0) + above;
                if (Sj >= kcur && Sn < kcur) {
                    s_prefix = prefix | ((unsigned)(lane * 8 + j) << shift);
                    s_k = kcur - Sn;
                }
            }
        }
        __syncthreads();
    }

    if (t == 0) d_thr[row] = s_prefix;   // exact key of K-th largest

#if __CUDA_ARCH__ >= 900
    cudaTriggerProgrammaticLaunchCompletion();   // let K3 start filling SMs
#endif
}

// ---------------------------------------------------------------------------
// K3: out = in * gate. One thread = one gate cell x 4 image rows:
// 1 gate load, 4 independent in loads (MLP=4, predicated off when dead),
// 4 stores. Warp per-instruction access = contiguous 512B.
// ---------------------------------------------------------------------------
__global__ void gate_mul_kernel(const float4* __restrict__ in,
                                float4* __restrict__ out) {
    int i  = blockIdx.x * blockDim.x + threadIdx.x;  // [0, 128*128)
    int x4 = i & 127;              // float4 col == gate col
    int gy = i >> 7;               // gate row
    int c  = blockIdx.y;           // channel
    int b  = blockIdx.z;           // batch

#if __CUDA_ARCH__ >= 900
    cudaGridDependencySynchronize();     // wait for select grid completion
#endif

    unsigned thr = __ldg(&d_thr[b]);
    float gv = d_gate[b * 16384 + gy * 128 + x4];
    bool alive = f2key(gv) >= thr;

    size_t base = (size_t)(b * 3 + c) * 65536 + (size_t)(4 * gy) * 128 + x4;

    float4 z = make_float4(0.f, 0.f, 0.f, 0.f);
    float4 v0 = z, v1 = z, v2 = z, v3 = z;
    if (alive) {
        float4 t0 = in[base];
        float4 t1 = in[base + 128];
        float4 t2 = in[base + 256];
        float4 t3 = in[base + 384];
        v0.x = t0.x * gv; v0.y = t0.y * gv; v0.z = t0.z * gv; v0.w = t0.w * gv;
        v1.x = t1.x * gv; v1.y = t1.y * gv; v1.z = t1.z * gv; v1.w = t1.w * gv;
        v2.x = t2.x * gv; v2.y = t2.y * gv; v2.z = t2.z * gv; v2.w = t2.w * gv;
        v3.x = t3.x * gv; v3.y = t3.y * gv; v3.z = t3.z * gv; v3.w = t3.w * gv;
    }
    out[base]       = v0;
    out[base + 128] = v1;
    out[base + 256] = v2;
    out[base + 384] = v3;
}

// ---------------------------------------------------------------------------
extern "C" void kernel_launch(void* const* d_in, const int* in_sizes, int n_in,
                              void* d_out, int out_size) {
    const float* inp = (const float*)d_in[0];
    const float* wk  = (const float*)d_in[1];
    if (n_in >= 2 && in_sizes[0] == 48) {  // defensive: swap if order flipped
        inp = (const float*)d_in[1];
        wk  = (const float*)d_in[0];
    }

    gate_conv_kernel<<<4096, 256>>>((const float4*)inp, wk);

    // K2 with PDL (fallback to plain launch if the attribute is rejected)
    {
        cudaLaunchConfig_t cfg = {};
        cfg.gridDim = dim3(64);
        cfg.blockDim = dim3(1024);
        cudaLaunchAttribute at[1];
        at[0].id = cudaLaunchAttributeProgrammaticStreamSerialization;
        at[0].val.programmaticStreamSerializationAllowed = 1;
        cfg.attrs = at;
        cfg.numAttrs = 1;
        if (cudaLaunchKernelEx(&cfg, gate_select_kernel) != cudaSuccess)
            gate_select_kernel<<<64, 1024>>>();
    }

    // K3 with PDL
    {
        cudaLaunchConfig_t cfg = {};
        cfg.gridDim = dim3(64, 3, 64);
        cfg.blockDim = dim3(256);
        cudaLaunchAttribute at[1];
        at[0].id = cudaLaunchAttributeProgrammaticStreamSerialization;
        at[0].val.programmaticStreamSerializationAllowed = 1;
        cfg.attrs = at;
        cfg.numAttrs = 1;
        if (cudaLaunchKernelEx(&cfg, gate_mul_kernel,
                               (const float4*)inp, (float4*)d_out)
            != cudaSuccess) {
            dim3 mgrid(64, 3, 64);
            gate_mul_kernel<<<mgrid, 256>>>((const float4*)inp,
                                            (float4*)d_out);
        }
    }
}